// round 10
// baseline (speedup 1.0000x reference)
#include <cuda_runtime.h>
#include <cuda_fp16.h>
#include <stdint.h>
#include <math.h>

// ---------------------------------------------------------------------------
// Problem dims
// ---------------------------------------------------------------------------
#define B_DIM 8192
#define IN_DIM 2048
#define H_DIM 2048
#define CAT_DIM 4096

#define OFF_NEWH    ((size_t)0)
#define OFF_CONCAT  (OFF_NEWH + (size_t)B_DIM * H_DIM)
#define OFF_PREGATE (OFF_CONCAT + (size_t)B_DIM * CAT_DIM)
#define OFF_GATE    (OFF_PREGATE + (size_t)B_DIM * H_DIM)
#define OFF_VALUES  (OFF_GATE + (size_t)B_DIM * H_DIM)
#define OFF_PREH    (OFF_VALUES + (size_t)B_DIM * H_DIM)

// ---------------------------------------------------------------------------
// Static device scratch
// ---------------------------------------------------------------------------
__device__ __half g_a_f16[(size_t)B_DIM * CAT_DIM];   // 64 MB concat fp16
__device__ __half g_w_f16[(size_t)H_DIM * CAT_DIM];   // 16 MB gate_w fp16
__device__ __half g_wi_f16[(size_t)H_DIM * IN_DIM];   //  8 MB w_i fp16
__device__ unsigned int g_unit_ctr;
__device__ int g_gate_flag[1024];

// ---------------------------------------------------------------------------
// Tiling: CTA tile 128x128, BK=32, 4-stage cp.async, frag double-buffer.
// smem row = 64B data + 16B pad = 80B (conflict-free ldmatrix phases)
// ---------------------------------------------------------------------------
#define ROWB 80
#define TILE_BYTES (128 * ROWB)            // 10240 per operand
#define STAGE_BYTES (2 * TILE_BYTES)       // 20480
#define NSTAGE 4
#define SMEM_TOTAL (NSTAGE * STAGE_BYTES)  // 81920
#define NTILES 1024
#define NUNITS 2048

__device__ __forceinline__ void hmma16816(float* c, const uint32_t* a,
                                          uint32_t b0, uint32_t b1) {
    asm volatile(
        "mma.sync.aligned.m16n8k16.row.col.f32.f16.f16.f32 "
        "{%0,%1,%2,%3},{%4,%5,%6,%7},{%8,%9},{%0,%1,%2,%3};"
        : "+f"(c[0]), "+f"(c[1]), "+f"(c[2]), "+f"(c[3])
        : "r"(a[0]), "r"(a[1]), "r"(a[2]), "r"(a[3]), "r"(b0), "r"(b1));
}

__device__ __forceinline__ void ldsm_x4(uint32_t* r, uint32_t addr) {
    asm volatile("ldmatrix.sync.aligned.m8n8.x4.shared.b16 {%0,%1,%2,%3}, [%4];"
                 : "=r"(r[0]), "=r"(r[1]), "=r"(r[2]), "=r"(r[3]) : "r"(addr));
}

__device__ __forceinline__ uint32_t smem_u32(const void* p) {
    uint32_t a;
    asm("{ .reg .u64 t; cvta.to.shared.u64 t, %1; cvt.u32.u64 %0, t; }"
        : "=r"(a) : "l"(p));
    return a;
}

__device__ __forceinline__ float clip01(float x) { return fminf(fmaxf(x, 0.0f), 1.0f); }

__device__ __forceinline__ float fast_tanh(float x) {
    if (fabsf(x) < 0.15f) {
        float t = x * x;
        return x * fmaf(t, fmaf(t, 0.13333334f, -0.33333334f), 1.0f);
    }
    return tanhf(x);
}

// Fragment bundle for one k-step: A 2x ldsm.x4, B 4x ldsm.x4
struct Frag {
    uint32_t a[2][4];
    uint32_t b[4][4];
};

// ---------------------------------------------------------------------------
// Prep kernel
// ---------------------------------------------------------------------------
__global__ void prep_kernel(const float4* __restrict__ input,
                            const float4* __restrict__ state,
                            const float4* __restrict__ gate_w,
                            const float4* __restrict__ w_i,
                            float* __restrict__ out) {
    size_t idx = (size_t)blockIdx.x * 256 + threadIdx.x;
    const size_t R1 = (size_t)B_DIM * CAT_DIM / 4;
    const size_t R2 = R1 + (size_t)H_DIM * CAT_DIM / 4;
    const size_t R3 = R2 + (size_t)H_DIM * IN_DIM / 4;

    if (blockIdx.x == 0) {
        if (threadIdx.x == 0) g_unit_ctr = 0;
        for (int i = threadIdx.x; i < NTILES; i += 256) g_gate_flag[i] = 0;
    }

    if (idx < R1) {
        size_t b = idx >> 10, c4 = idx & 1023;
        float4 v = (c4 < 512) ? input[b * 512 + c4] : state[b * 512 + (c4 - 512)];
        ((float4*)(out + OFF_CONCAT))[idx] = v;
        ((__half2*)g_a_f16)[idx * 2]     = __floats2half2_rn(v.x, v.y);
        ((__half2*)g_a_f16)[idx * 2 + 1] = __floats2half2_rn(v.z, v.w);
    } else if (idx < R2) {
        size_t j = idx - R1;
        float4 v = gate_w[j];
        ((__half2*)g_w_f16)[j * 2]     = __floats2half2_rn(v.x, v.y);
        ((__half2*)g_w_f16)[j * 2 + 1] = __floats2half2_rn(v.z, v.w);
    } else if (idx < R3) {
        size_t j = idx - R2;
        float4 v = w_i[j];
        ((__half2*)g_wi_f16)[j * 2]     = __floats2half2_rn(v.x, v.y);
        ((__half2*)g_wi_f16)[j * 2 + 1] = __floats2half2_rn(v.z, v.w);
    }
}

// ---------------------------------------------------------------------------
// Stage loader: 1024 x 16B cp.async
// ---------------------------------------------------------------------------
__device__ __forceinline__ void load_tile(uint32_t sbase, const char* aptr,
                                          const char* bptr, size_t bstride,
                                          int koff, int tid) {
#pragma unroll
    for (int j = 0; j < 4; j++) {
        int gid = tid + j * 256;
        uint32_t dst;
        const char* src;
        if (gid < 512) {
            int row = gid >> 2, c = gid & 3;
            dst = sbase + row * ROWB + c * 16;
            src = aptr + (size_t)row * 8192 + koff + c * 16;
        } else {
            int g = gid - 512;
            int row = g >> 2, c = g & 3;
            dst = sbase + TILE_BYTES + row * ROWB + c * 16;
            src = bptr + (size_t)row * bstride + koff + c * 16;
        }
        asm volatile("cp.async.cg.shared.global [%0], [%1], 16;"
                     :: "r"(dst), "l"(src) : "memory");
    }
    asm volatile("cp.async.commit_group;" ::: "memory");
}

// ---------------------------------------------------------------------------
// Persistent merged GEMM with fragment double-buffering.
// ---------------------------------------------------------------------------
__global__ __launch_bounds__(256, 2)
void gemm_persist(const float* __restrict__ gate_b,
                  const float* __restrict__ state,
                  float* __restrict__ out) {
    extern __shared__ __align__(128) char smem[];
    __shared__ unsigned s_unit;

    const int tid  = threadIdx.x;
    const int lane = tid & 31;
    const int warp = tid >> 5;
    const int wm = warp >> 1;
    const int wn = warp & 1;
    const int fr = lane >> 2;
    const int fc = lane & 3;

    const uint32_t smem32 = smem_u32(smem);

    uint32_t A_off[2], B_off[4];
#pragma unroll
    for (int mi = 0; mi < 2; mi++)
        A_off[mi] = (wm * 32 + mi * 16 + (lane & 15)) * ROWB + ((lane >> 4) * 16);
#pragma unroll
    for (int q = 0; q < 4; q++)
        B_off[q] = TILE_BYTES +
                   (wn * 64 + q * 16 + (lane & 7) + ((lane >> 4) << 3)) * ROWB +
                   (((lane >> 3) & 1) * 16);

    const char* const a_root  = (const char*)g_a_f16;
    const char* const w_root  = (const char*)g_w_f16;
    const char* const wi_root = (const char*)g_wi_f16;

    for (;;) {
        __syncthreads();
        if (tid == 0) s_unit = atomicAdd(&g_unit_ctr, 1u);
        __syncthreads();
        const unsigned u = s_unit;
        if (u >= NUNITS) break;

        const int mode = (u >= NTILES);
        const int t = u & (NTILES - 1);
        const int bm = (t >> 4) * 128;
        const int bn = (t & 15) * 128;

        const char* aptr = a_root + (size_t)bm * 8192;
        const char* bptr;
        size_t bstride;
        int nit;
        if (!mode) { bptr = w_root  + (size_t)bn * 8192; bstride = 8192; nit = 128; }
        else       { bptr = wi_root + (size_t)bn * 4096; bstride = 4096; nit = 64;  }

        float acc[2][8][4];
#pragma unroll
        for (int i = 0; i < 2; i++)
#pragma unroll
            for (int j = 0; j < 8; j++)
#pragma unroll
                for (int k = 0; k < 4; k++) acc[i][j][k] = 0.0f;

        // Prologue: 3 stages in flight, then frag-load ks0 of stage 0.
        load_tile(smem32 + 0 * STAGE_BYTES, aptr, bptr, bstride, 0, tid);
        load_tile(smem32 + 1 * STAGE_BYTES, aptr, bptr, bstride, 64, tid);
        load_tile(smem32 + 2 * STAGE_BYTES, aptr, bptr, bstride, 128, tid);
        asm volatile("cp.async.wait_group 2;" ::: "memory");
        __syncthreads();

        Frag f0, f1;
        {
            const uint32_t sb = smem32;
            ldsm_x4(f0.a[0], sb + A_off[0]);
            ldsm_x4(f0.a[1], sb + A_off[1]);
#pragma unroll
            for (int q = 0; q < 4; q++) ldsm_x4(f0.b[q], sb + B_off[q]);
        }

        int stage = 0;
        for (int it = 0; it < nit; ++it) {
            const uint32_t sb = smem32 + stage * STAGE_BYTES;

            // A: load ks1 frags of current stage into f1
            ldsm_x4(f1.a[0], sb + A_off[0] + 32);
            ldsm_x4(f1.a[1], sb + A_off[1] + 32);
#pragma unroll
            for (int q = 0; q < 4; q++) ldsm_x4(f1.b[q], sb + B_off[q] + 32);

            // B: MMA on ks0 frags (f0) — hides f1's LDSM latency
#pragma unroll
            for (int ni = 0; ni < 8; ni++) {
                uint32_t b0 = f0.b[ni >> 1][(ni & 1) * 2];
                uint32_t b1 = f0.b[ni >> 1][(ni & 1) * 2 + 1];
                hmma16816(acc[0][ni], f0.a[0], b0, b1);
                hmma16816(acc[1][ni], f0.a[1], b0, b1);
            }

            // C: issue prefetch for iter it+3 (stage (stage+3)&3)
            if (it + 3 < nit)
                load_tile(smem32 + ((stage + 3) & 3) * STAGE_BYTES,
                          aptr, bptr, bstride, (it + 3) * 64, tid);

            // D/E: advance stage boundary, load ks0 frags of next stage into f0
            if (it + 1 < nit) {
                if (it + 3 < nit)      asm volatile("cp.async.wait_group 2;" ::: "memory");
                else if (it == nit - 3) asm volatile("cp.async.wait_group 1;" ::: "memory");
                else                   asm volatile("cp.async.wait_group 0;" ::: "memory");
                __syncthreads();
                const uint32_t nb = smem32 + ((stage + 1) & 3) * STAGE_BYTES;
                ldsm_x4(f0.a[0], nb + A_off[0]);
                ldsm_x4(f0.a[1], nb + A_off[1]);
#pragma unroll
                for (int q = 0; q < 4; q++) ldsm_x4(f0.b[q], nb + B_off[q]);
            }

            // F: MMA on ks1 frags (f1) — hides f0's LDSM latency
#pragma unroll
            for (int ni = 0; ni < 8; ni++) {
                uint32_t b0 = f1.b[ni >> 1][(ni & 1) * 2];
                uint32_t b1 = f1.b[ni >> 1][(ni & 1) * 2 + 1];
                hmma16816(acc[0][ni], f1.a[0], b0, b1);
                hmma16816(acc[1][ni], f1.a[1], b0, b1);
            }

            stage = (stage + 1) & 3;
        }

        // ---------------- Epilogue ----------------
        if (!mode) {
            float* out_pg = out + OFF_PREGATE;
            float* out_g  = out + OFF_GATE;
#pragma unroll
            for (int mi = 0; mi < 2; mi++) {
#pragma unroll
                for (int ni = 0; ni < 8; ni++) {
                    int r = bm + wm * 32 + mi * 16 + fr;
                    int c = bn + wn * 64 + ni * 8 + fc * 2;
                    float b0 = gate_b[c], b1 = gate_b[c + 1];
                    float pg0 = acc[mi][ni][0] + b0;
                    float pg1 = acc[mi][ni][1] + b1;
                    float pg2 = acc[mi][ni][2] + b0;
                    float pg3 = acc[mi][ni][3] + b1;
                    *(float2*)&out_pg[(size_t)r * H_DIM + c]       = make_float2(pg0, pg1);
                    *(float2*)&out_pg[(size_t)(r + 8) * H_DIM + c] = make_float2(pg2, pg3);
                    *(float2*)&out_g[(size_t)r * H_DIM + c]        = make_float2(clip01(pg0), clip01(pg1));
                    *(float2*)&out_g[(size_t)(r + 8) * H_DIM + c]  = make_float2(clip01(pg2), clip01(pg3));
                }
            }
            __threadfence();
            __syncthreads();
            if (tid == 0) atomicExch(&g_gate_flag[t], 1);
        } else {
            if (tid == 0) {
                while (atomicAdd(&g_gate_flag[t], 0) == 0) { __nanosleep(64); }
                __threadfence();
            }
            __syncthreads();
            const float* gate = out + OFF_GATE;
#pragma unroll
            for (int mi = 0; mi < 2; mi++) {
#pragma unroll
                for (int ni = 0; ni < 8; ni++) {
                    int r = bm + wm * 32 + mi * 16 + fr;
                    int c = bn + wn * 64 + ni * 8 + fc * 2;
#pragma unroll
                    for (int half = 0; half < 2; half++) {
                        size_t o = (size_t)(r + half * 8) * H_DIM + c;
                        float v0 = fast_tanh(acc[mi][ni][half * 2 + 0]);
                        float v1 = fast_tanh(acc[mi][ni][half * 2 + 1]);
                        float2 g = *(const float2*)&gate[o];
                        float2 s = *(const float2*)&state[o];
                        float ph0 = s.x * (1.0f - g.x) + v0 * g.x;
                        float ph1 = s.y * (1.0f - g.y) + v1 * g.y;
                        *(float2*)&out[OFF_VALUES + o] = make_float2(v0, v1);
                        *(float2*)&out[OFF_PREH + o]   = make_float2(ph0, ph1);
                        *(float2*)&out[OFF_NEWH + o]   = make_float2(fmaxf(ph0, 0.0f),
                                                                    fmaxf(ph1, 0.0f));
                    }
                }
            }
        }
    }
}

// ---------------------------------------------------------------------------
extern "C" void kernel_launch(void* const* d_in, const int* in_sizes, int n_in,
                              void* d_out, int out_size) {
    const float* input  = (const float*)d_in[0];
    const float* state  = (const float*)d_in[1];
    const float* gate_w = (const float*)d_in[2];
    const float* gate_b = (const float*)d_in[3];
    const float* w_i    = (const float*)d_in[4];
    float* out = (float*)d_out;

    cudaFuncSetAttribute(gemm_persist,
                         cudaFuncAttributeMaxDynamicSharedMemorySize, SMEM_TOTAL);

    prep_kernel<<<45056, 256>>>((const float4*)input, (const float4*)state,
                                (const float4*)gate_w, (const float4*)w_i, out);

    gemm_persist<<<296, 256, SMEM_TOTAL>>>(gate_b, state, out);
}